// round 7
// baseline (speedup 1.0000x reference)
#include <cuda_runtime.h>
#include <cuda_bf16.h>

// SparseToDense via inverse-gather with collision chains.
//   1) memset node: g_inv[:] = -1
//   2) build: atomicExch head insert + chain link
//   3) persistent gather: each block owns ~18 tiles. The SMEM tile is zeroed
//      ONCE; the drain restores zeros behind itself (zero-maintenance), so no
//      per-tile zero fill and no per-element masking — only a 32-bit quad mask.
//
// SMEM tile layout: tile[c][pq][e], pq = ((sp>>2) + c) & 31, e = sp & 3.
//   fill  (per active cell, c = lane / lane+32):   conflict-free
//   drain (per channel, physical quad = lane):     linear LDS.128, rotation
//          folded into the STG address (quad permutation within 512B -> coalesced)

#define TILE 128
#define NTHREADS 256
#define MAX_BS3 (4 * 1024 * 1024)
#define MAX_N   (4 * 1024 * 1024)
#define C64 64

__device__ int g_inv[MAX_BS3];
__device__ int g_next[MAX_N];

__global__ void build_inv(const int* __restrict__ idx, int N, int BS3) {
    int n = blockIdx.x * blockDim.x + threadIdx.x;
    if (n >= N) return;
    int r = idx[n];
    if ((unsigned)r >= (unsigned)BS3) return;       // defensive
    int old = atomicExch(&g_inv[r], n);             // push-front
    g_next[n] = old;                                // coalesced chain link
}

__global__ __launch_bounds__(NTHREADS, 6)
void gather_write(const float* __restrict__ feats,
                  const int* __restrict__ s_ptr,
                  float* __restrict__ out, int BS3) {
    __shared__ float tile[C64 * TILE];   // 32 KB, rotated; kept zero between tiles
    __shared__ int list_sp[TILE];
    __shared__ int list_n[TILE];
    __shared__ unsigned qmask;           // bit per logical quad (32 quads)
    __shared__ int lcnt;

    const int S  = s_ptr[0];
    const int S3 = S * S * S;
    const int tid  = threadIdx.x;
    const int lane = tid & 31;
    const int wid  = tid >> 5;            // 0..7
    const int ntiles = BS3 / TILE;        // BS3 % TILE == 0 for this problem

    // Zero the tile ONCE per block (amortized over ~18 tiles).
    float4* tz = reinterpret_cast<float4*>(tile);
    #pragma unroll
    for (int i = tid; i < (C64 * TILE) / 4; i += NTHREADS)
        tz[i] = make_float4(0.f, 0.f, 0.f, 0.f);

    for (int t = blockIdx.x; t < ntiles; t += gridDim.x) {
        const int g0 = t * TILE;

        __syncthreads();                  // prev drain done (qmask/list/tile free)
        if (tid == 0) { lcnt = 0; qmask = 0u; }
        __syncthreads();                  // reset visible

        // Compact active cells + build quad mask.
        if (tid < TILE) {
            int n = g_inv[g0 + tid];
            if (n >= 0) {
                int p = atomicAdd(&lcnt, 1);
                list_sp[p] = tid;
                list_n[p]  = n;
                atomicOr(&qmask, 1u << (tid >> 2));
            }
        }
        __syncthreads();                  // list + qmask ready

        // Warp-per-cell coalesced feature fetch, chain-summed, rotated store.
        for (int i = wid; i < lcnt; i += (NTHREADS >> 5)) {
            int sp = list_sp[i];
            int n  = list_n[i];
            float a0 = 0.0f, a1 = 0.0f;
            while (n >= 0) {                         // length 1 for ~99%
                const float* row = feats + (long long)n * C64;
                a0 += row[lane];
                a1 += row[lane + 32];
                n = g_next[n];                       // warp-uniform load
            }
            int sp4 = sp >> 2, e = sp & 3;
            int pq = (sp4 + lane) & 31;              // same rotation both halves
            tile[lane * TILE + pq * 4 + e]        = a0;
            tile[(lane + 32) * TILE + pq * 4 + e] = a1;
        }
        __syncthreads();                  // tile ready

        // Drain: warp owns 8 channels; lane reads physical quad `lane`.
        // Active quads: LDS.128 + restore zeros behind us (same address, same
        // thread -> race-free). Inactive quads: constant-zero store, no LDS.
        const int b = g0 / S3;
        const long long s3 = S3;
        float* obase = out + (long long)b * C64 * s3 + (g0 - (long long)b * s3);
        float4* trow = reinterpret_cast<float4*>(tile);
        const unsigned qm = qmask;
        const float4 z4 = make_float4(0.f, 0.f, 0.f, 0.f);
        #pragma unroll
        for (int i = 0; i < 8; i++) {
            int c  = wid * 8 + i;
            int lq = (lane - c) & 31;                // logical quad for this lane
            float4 v = z4;
            if ((qm >> lq) & 1u) {
                v = trow[c * (TILE / 4) + lane];     // linear, conflict-free
                trow[c * (TILE / 4) + lane] = z4;    // zero-maintenance
            }
            __stcs(reinterpret_cast<float4*>(obase + c * s3) + lq, v);
        }
    }
}

extern "C" void kernel_launch(void* const* d_in, const int* in_sizes, int n_in,
                              void* d_out, int out_size) {
    const float* feats = (const float*)d_in[0];
    const int*   idx   = (const int*)d_in[1];
    const int*   s_ptr = (const int*)d_in[2];
    float*       out   = (float*)d_out;

    const int N   = in_sizes[1];           // 262144 active sites
    const int BS3 = out_size / C64;        // B * S^3 = 2M

    void* inv_ptr = nullptr;
    cudaGetSymbolAddress(&inv_ptr, g_inv);
    cudaMemsetAsync(inv_ptr, 0xFF, (size_t)BS3 * sizeof(int), 0);

    build_inv<<<(N + 255) / 256, 256>>>(idx, N, BS3);

    int ntiles = BS3 / TILE;
    int blocks = 148 * 6;                  // persistent: 6 CTAs/SM (smem-bound)
    if (blocks > ntiles) blocks = ntiles;
    gather_write<<<blocks, NTHREADS>>>(feats, s_ptr, out, BS3);
}